// round 1
// baseline (speedup 1.0000x reference)
#include <cuda_runtime.h>
#include <math.h>

#define DM 512
#define NH 8
#define HD 64
#define DFF 2048
#define BB 2
#define SS 2048
#define NT (BB*SS)   // 4096 tokens

// ---------------- static device scratch (allocation-free) ----------------
__device__ float g_q[NT * DM];
__device__ float g_k[NT * DM];
__device__ float g_v[NT * DM];
__device__ float g_ctx[NT * DM];
__device__ float g_ao[NT * DM];
__device__ float g_h[NT * DM];
__device__ float g_ff1[NT * DFF];
__device__ float g_ff2[NT * DM];
__device__ float g_sc[(size_t)BB * NH * SS * SS];   // 67.1M floats = 256 MB

// ---------------- generic tiled GEMM: C[M,N] = A[M,K] @ W[K,N] + bias ----------------
// 64x64 output tile per 256-thread block, 4x4 per thread, BK=16.
template<bool RELU>
__global__ void gemm_bias_kernel(const float* __restrict__ A,
                                 const float* __restrict__ W,
                                 const float* __restrict__ bias,
                                 float* __restrict__ C,
                                 int M, int K, int N)
{
    __shared__ float As[64][17];   // [m][k], padded (store: 16 consecutive k per row)
    __shared__ float Bs[16][64];   // [k][n]

    const int tid = threadIdx.x;
    const int tx = tid & 15;       // output col group
    const int ty = tid >> 4;       // output row group
    const int row0 = blockIdx.y * 64;
    const int col0 = blockIdx.x * 64;

    float acc[4][4] = {};

    for (int k0 = 0; k0 < K; k0 += 16) {
        // load A tile 64x16 (each thread 4 elems; consecutive threads -> consecutive k)
        #pragma unroll
        for (int t = 0; t < 4; t++) {
            int idx = tid + t * 256;       // 0..1023
            int m  = idx >> 4;
            int kk = idx & 15;
            As[m][kk] = A[(size_t)(row0 + m) * K + k0 + kk];
        }
        // load B tile 16x64 (consecutive threads -> consecutive n, coalesced)
        #pragma unroll
        for (int t = 0; t < 4; t++) {
            int idx = tid + t * 256;
            int kk = idx >> 6;
            int n  = idx & 63;
            Bs[kk][n] = W[(size_t)(k0 + kk) * N + col0 + n];
        }
        __syncthreads();

        #pragma unroll
        for (int kk = 0; kk < 16; kk++) {
            float a[4], b[4];
            #pragma unroll
            for (int i = 0; i < 4; i++) a[i] = As[ty * 4 + i][kk];
            #pragma unroll
            for (int j = 0; j < 4; j++) b[j] = Bs[kk][tx * 4 + j];
            #pragma unroll
            for (int i = 0; i < 4; i++)
                #pragma unroll
                for (int j = 0; j < 4; j++)
                    acc[i][j] = fmaf(a[i], b[j], acc[i][j]);
        }
        __syncthreads();
    }

    #pragma unroll
    for (int i = 0; i < 4; i++) {
        int m = row0 + ty * 4 + i;
        #pragma unroll
        for (int j = 0; j < 4; j++) {
            int n = col0 + tx * 4 + j;
            float v = acc[i][j] + bias[n];
            if (RELU) v = fmaxf(v, 0.0f);
            C[(size_t)m * N + n] = v;
        }
    }
}

// ---------------- attention scores: sc[bh][i][j] = (q_i . k_j) / 8 ----------------
// grid: (S/64, S/64, B*NH); full Dh=64 in smem, one pass.
__global__ void attn_scores_kernel(const float* __restrict__ q,
                                   const float* __restrict__ k,
                                   float* __restrict__ sc)
{
    __shared__ float Qs[64][65];
    __shared__ float Ks[64][65];

    const int tid = threadIdx.x;
    const int tx = tid & 15;
    const int ty = tid >> 4;
    const int bh = blockIdx.z;
    const int b = bh >> 3;
    const int h = bh & 7;

    const float* qb = q + (size_t)b * SS * DM + h * HD;
    const float* kb = k + (size_t)b * SS * DM + h * HD;
    float* scb = sc + (size_t)bh * SS * SS;

    const int i0 = blockIdx.y * 64;
    const int j0 = blockIdx.x * 64;

    #pragma unroll
    for (int t = 0; t < 16; t++) {
        int idx = tid + t * 256;   // 0..4095
        int r = idx >> 6;
        int c = idx & 63;
        Qs[r][c] = qb[(size_t)(i0 + r) * DM + c];
        Ks[r][c] = kb[(size_t)(j0 + r) * DM + c];
    }
    __syncthreads();

    float acc[4][4] = {};
    #pragma unroll 16
    for (int kk = 0; kk < 64; kk++) {
        float a[4], bb[4];
        #pragma unroll
        for (int i = 0; i < 4; i++) a[i] = Qs[ty * 4 + i][kk];
        #pragma unroll
        for (int j = 0; j < 4; j++) bb[j] = Ks[tx * 4 + j][kk];
        #pragma unroll
        for (int i = 0; i < 4; i++)
            #pragma unroll
            for (int j = 0; j < 4; j++)
                acc[i][j] = fmaf(a[i], bb[j], acc[i][j]);
    }

    #pragma unroll
    for (int i = 0; i < 4; i++)
        #pragma unroll
        for (int j = 0; j < 4; j++)
            scb[(size_t)(i0 + ty * 4 + i) * SS + (j0 + tx * 4 + j)] = acc[i][j] * 0.125f;
}

// ---------------- row softmax over 2048 elements, one block per row ----------------
__global__ void softmax_kernel(float* __restrict__ sc)
{
    __shared__ float red[256];
    float* p = sc + (size_t)blockIdx.x * SS;
    const int t = threadIdx.x;

    float vals[8];
    float m = -1e30f;
    #pragma unroll
    for (int i = 0; i < 8; i++) {
        vals[i] = p[t + i * 256];
        m = fmaxf(m, vals[i]);
    }
    red[t] = m; __syncthreads();
    for (int s = 128; s > 0; s >>= 1) {
        if (t < s) red[t] = fmaxf(red[t], red[t + s]);
        __syncthreads();
    }
    m = red[0];
    __syncthreads();

    float sum = 0.0f;
    #pragma unroll
    for (int i = 0; i < 8; i++) {
        vals[i] = __expf(vals[i] - m);
        sum += vals[i];
    }
    red[t] = sum; __syncthreads();
    for (int s = 128; s > 0; s >>= 1) {
        if (t < s) red[t] += red[t + s];
        __syncthreads();
    }
    float inv = 1.0f / red[0];
    #pragma unroll
    for (int i = 0; i < 8; i++)
        p[t + i * 256] = vals[i] * inv;
}

// ---------------- ctx[bh][i][:] = attn[bh][i][:] @ V_h ----------------
// grid: (S/64, B*NH); output tile 64 x 64 (full Dh).
__global__ void attn_ctx_kernel(const float* __restrict__ sc,
                                const float* __restrict__ v,
                                float* __restrict__ ctx)
{
    __shared__ float Ps[64][65];   // attn tile [qrow][kcol]
    __shared__ float Vs[64][65];   // V tile [krow][d]

    const int tid = threadIdx.x;
    const int tx = tid & 15;
    const int ty = tid >> 4;
    const int bh = blockIdx.y;
    const int b = bh >> 3;
    const int h = bh & 7;

    const float* scb = sc + (size_t)bh * SS * SS;
    const float* vb = v + (size_t)b * SS * DM + h * HD;
    float* cb = ctx + (size_t)b * SS * DM + h * HD;

    const int i0 = blockIdx.x * 64;
    float acc[4][4] = {};

    for (int j0 = 0; j0 < SS; j0 += 64) {
        #pragma unroll
        for (int t = 0; t < 16; t++) {
            int idx = tid + t * 256;
            int r = idx >> 6;
            int c = idx & 63;
            Ps[r][c] = scb[(size_t)(i0 + r) * SS + j0 + c];
            Vs[r][c] = vb[(size_t)(j0 + r) * DM + c];
        }
        __syncthreads();

        #pragma unroll 16
        for (int kk = 0; kk < 64; kk++) {
            float a[4], bb[4];
            #pragma unroll
            for (int i = 0; i < 4; i++) a[i] = Ps[ty * 4 + i][kk];
            #pragma unroll
            for (int j = 0; j < 4; j++) bb[j] = Vs[kk][tx * 4 + j];
            #pragma unroll
            for (int i = 0; i < 4; i++)
                #pragma unroll
                for (int j = 0; j < 4; j++)
                    acc[i][j] = fmaf(a[i], bb[j], acc[i][j]);
        }
        __syncthreads();
    }

    #pragma unroll
    for (int i = 0; i < 4; i++)
        #pragma unroll
        for (int j = 0; j < 4; j++)
            cb[(size_t)(i0 + ty * 4 + i) * DM + tx * 4 + j] = acc[i][j];
}

// ---------------- out = LayerNorm(a + b) * g + be, one block per token row ----------------
__global__ void add_ln_kernel(const float* __restrict__ xa,
                              const float* __restrict__ xb,
                              const float* __restrict__ g,
                              const float* __restrict__ be,
                              float* __restrict__ out)
{
    __shared__ float red[256];
    const int row = blockIdx.x;
    const int t = threadIdx.x;
    const float* pa = xa + (size_t)row * DM;
    const float* pb = xb + (size_t)row * DM;

    float v0 = pa[t] + pb[t];
    float v1 = pa[t + 256] + pb[t + 256];

    red[t] = v0 + v1; __syncthreads();
    for (int s = 128; s > 0; s >>= 1) {
        if (t < s) red[t] += red[t + s];
        __syncthreads();
    }
    float mu = red[0] * (1.0f / DM);
    __syncthreads();

    float d0 = v0 - mu, d1 = v1 - mu;
    red[t] = d0 * d0 + d1 * d1; __syncthreads();
    for (int s = 128; s > 0; s >>= 1) {
        if (t < s) red[t] += red[t + s];
        __syncthreads();
    }
    float r = rsqrtf(red[0] * (1.0f / DM) + 1e-5f);

    out[(size_t)row * DM + t]       = d0 * r * g[t]       + be[t];
    out[(size_t)row * DM + t + 256] = d1 * r * g[t + 256] + be[t + 256];
}

// ---------------- launch ----------------
extern "C" void kernel_launch(void* const* d_in, const int* in_sizes, int n_in,
                              void* d_out, int out_size)
{
    const float* x   = (const float*)d_in[0];
    const float* Wq  = (const float*)d_in[1];
    const float* bq  = (const float*)d_in[2];
    const float* Wk  = (const float*)d_in[3];
    const float* bk  = (const float*)d_in[4];
    const float* Wv  = (const float*)d_in[5];
    const float* bv  = (const float*)d_in[6];
    const float* Wo  = (const float*)d_in[7];
    const float* bo  = (const float*)d_in[8];
    const float* W1  = (const float*)d_in[9];
    const float* b1  = (const float*)d_in[10];
    const float* W2  = (const float*)d_in[11];
    const float* b2  = (const float*)d_in[12];
    const float* g1  = (const float*)d_in[13];
    const float* be1 = (const float*)d_in[14];
    const float* g2  = (const float*)d_in[15];
    const float* be2 = (const float*)d_in[16];

    float *q, *k, *v, *sc, *ctx, *ao, *h, *ff1, *ff2;
    cudaGetSymbolAddress((void**)&q,   g_q);
    cudaGetSymbolAddress((void**)&k,   g_k);
    cudaGetSymbolAddress((void**)&v,   g_v);
    cudaGetSymbolAddress((void**)&sc,  g_sc);
    cudaGetSymbolAddress((void**)&ctx, g_ctx);
    cudaGetSymbolAddress((void**)&ao,  g_ao);
    cudaGetSymbolAddress((void**)&h,   g_h);
    cudaGetSymbolAddress((void**)&ff1, g_ff1);
    cudaGetSymbolAddress((void**)&ff2, g_ff2);

    // Q, K, V projections: [4096,512] @ [512,512]
    gemm_bias_kernel<false><<<dim3(DM / 64, NT / 64), 256>>>(x, Wq, bq, q, NT, DM, DM);
    gemm_bias_kernel<false><<<dim3(DM / 64, NT / 64), 256>>>(x, Wk, bk, k, NT, DM, DM);
    gemm_bias_kernel<false><<<dim3(DM / 64, NT / 64), 256>>>(x, Wv, bv, v, NT, DM, DM);

    // attention
    attn_scores_kernel<<<dim3(SS / 64, SS / 64, BB * NH), 256>>>(q, k, sc);
    softmax_kernel<<<BB * NH * SS, 256>>>(sc);
    attn_ctx_kernel<<<dim3(SS / 64, BB * NH), 256>>>(sc, v, ctx);

    // output projection + residual 1 + LN1
    gemm_bias_kernel<false><<<dim3(DM / 64, NT / 64), 256>>>(ctx, Wo, bo, ao, NT, DM, DM);
    add_ln_kernel<<<NT, 256>>>(x, ao, g1, be1, h);

    // FFN + residual 2 + LN2
    gemm_bias_kernel<true><<<dim3(DFF / 64, NT / 64), 256>>>(h, W1, b1, ff1, NT, DM, DFF);
    gemm_bias_kernel<false><<<dim3(DM / 64, NT / 64), 256>>>(ff1, W2, b2, ff2, NT, DFF, DM);
    add_ln_kernel<<<NT, 256>>>(h, ff2, g2, be2, (float*)d_out);
}

// round 3
// speedup vs baseline: 2.7188x; 2.7188x over previous
#include <cuda_runtime.h>
#include <cuda_bf16.h>
#include <cstdint>
#include <math.h>

#define DM 512
#define NH 8
#define HD 64
#define DFF 2048
#define BB 2
#define SS 2048
#define NT (BB*SS)
#define BH (BB*NH)

#define SWZ(off) ((off) ^ (((off) >> 3) & 0x70))

__device__ __forceinline__ uint32_t smem_to_u32(const void* smem_ptr) {
    uint32_t addr;
    asm("{ .reg .u64 tmp; cvta.to.shared.u64 tmp, %1; cvt.u32.u64 %0, tmp; }"
        : "=r"(addr) : "l"(smem_ptr));
    return addr;
}

#define LDMATRIX_X4(r, addr) \
    asm volatile("ldmatrix.sync.aligned.m8n8.x4.shared.b16 {%0,%1,%2,%3}, [%4];" \
        : "=r"((r)[0]), "=r"((r)[1]), "=r"((r)[2]), "=r"((r)[3]) : "r"(addr))

#define MMA_BF16(c, a, b0, b1) \
    asm volatile("mma.sync.aligned.m16n8k16.row.col.f32.bf16.bf16.f32 " \
        "{%0,%1,%2,%3}, {%4,%5,%6,%7}, {%8,%9}, {%0,%1,%2,%3};" \
        : "+f"((c)[0]), "+f"((c)[1]), "+f"((c)[2]), "+f"((c)[3]) \
        : "r"((a)[0]), "r"((a)[1]), "r"((a)[2]), "r"((a)[3]), "r"(b0), "r"(b1))

// ===================== static device scratch =====================
__device__ float g_sc[(size_t)BH * SS * SS];
__device__ __nv_bfloat16 g_p_hi[(size_t)BH * SS * SS];
__device__ __nv_bfloat16 g_p_lo[(size_t)BH * SS * SS];

__device__ __nv_bfloat16 g_x_hi[NT * DM],  g_x_lo[NT * DM];
__device__ __nv_bfloat16 g_q_hi[NT * DM],  g_q_lo[NT * DM];
__device__ __nv_bfloat16 g_k_hi[NT * DM],  g_k_lo[NT * DM];
__device__ __nv_bfloat16 g_v_hi[NT * DM],  g_v_lo[NT * DM];
__device__ __nv_bfloat16 g_vt_hi[NT * DM], g_vt_lo[NT * DM];   // [bh][d][s]
__device__ __nv_bfloat16 g_ctx_hi[NT * DM], g_ctx_lo[NT * DM];
__device__ __nv_bfloat16 g_h_hi[NT * DM],  g_h_lo[NT * DM];
__device__ __nv_bfloat16 g_f1_hi[NT * DFF], g_f1_lo[NT * DFF];

__device__ __nv_bfloat16 g_wq_hi[DM * DM], g_wq_lo[DM * DM];   // [N,K]
__device__ __nv_bfloat16 g_wk_hi[DM * DM], g_wk_lo[DM * DM];
__device__ __nv_bfloat16 g_wv_hi[DM * DM], g_wv_lo[DM * DM];
__device__ __nv_bfloat16 g_wo_hi[DM * DM], g_wo_lo[DM * DM];
__device__ __nv_bfloat16 g_w1_hi[DM * DFF], g_w1_lo[DM * DFF];
__device__ __nv_bfloat16 g_w2_hi[DM * DFF], g_w2_lo[DM * DFF];

__device__ float g_ao[NT * DM];
__device__ float g_h[NT * DM];
__device__ float g_ff2[NT * DM];

// ===================== helpers =====================
__device__ __forceinline__ void split_bf16(float x, __nv_bfloat16& h, __nv_bfloat16& l) {
    h = __float2bfloat16(x);
    l = __float2bfloat16(x - __bfloat162float(h));
}

__global__ void cvt_kernel(const float* __restrict__ in,
                           __nv_bfloat16* __restrict__ hi,
                           __nv_bfloat16* __restrict__ lo, int n)
{
    int i = blockIdx.x * 256 + threadIdx.x;
    if (i < n) { __nv_bfloat16 h, l; split_bf16(in[i], h, l); hi[i] = h; lo[i] = l; }
}

// W[K,N] fp32 -> WT[N,K] hi/lo bf16
__global__ void wtrans_kernel(const float* __restrict__ W, int K, int N,
                              __nv_bfloat16* __restrict__ Thi,
                              __nv_bfloat16* __restrict__ Tlo)
{
    __shared__ float tile[32][33];
    int n0 = blockIdx.x * 32, k0 = blockIdx.y * 32;
    int tx = threadIdx.x & 31, ty = threadIdx.x >> 5;
    #pragma unroll
    for (int i = 0; i < 32; i += 8)
        tile[ty + i][tx] = W[(size_t)(k0 + ty + i) * N + n0 + tx];
    __syncthreads();
    #pragma unroll
    for (int i = 0; i < 32; i += 8) {
        float v = tile[tx][ty + i];
        __nv_bfloat16 h, l; split_bf16(v, h, l);
        size_t dst = (size_t)(n0 + ty + i) * K + k0 + tx;
        Thi[dst] = h; Tlo[dst] = l;
    }
}

// v planes [token, h*64+d] -> vT planes [bh][d][s]
__global__ void vtrans_kernel(const __nv_bfloat16* __restrict__ vh,
                              const __nv_bfloat16* __restrict__ vl,
                              __nv_bfloat16* __restrict__ oth,
                              __nv_bfloat16* __restrict__ otl)
{
    __shared__ unsigned short th[64][65];
    __shared__ unsigned short tl[64][65];
    int bh = blockIdx.y; int b = bh >> 3, h = bh & 7;
    int s0 = blockIdx.x * 64;
    for (int i = threadIdx.x; i < 64 * 64; i += 256) {
        int r = i >> 6, c = i & 63;
        size_t src = (size_t)(b * SS + s0 + r) * DM + h * 64 + c;
        th[r][c] = ((const unsigned short*)vh)[src];
        tl[r][c] = ((const unsigned short*)vl)[src];
    }
    __syncthreads();
    for (int i = threadIdx.x; i < 64 * 64; i += 256) {
        int d = i >> 6, s = i & 63;
        size_t dst = ((size_t)bh * 64 + d) * SS + s0 + s;
        ((unsigned short*)oth)[dst] = th[s][d];
        ((unsigned short*)otl)[dst] = tl[s][d];
    }
}

// ===================== split-bf16 mma.sync GEMM =====================
// D[128,64] tile = A @ B^T. A planes [M,K] row stride lda; B planes [N,K] row stride ldb.
// z-offset per operand: off = (z>>3)*s1 + (z&7)*s2.
// EPI: 0 none, 1 +bias, 2 +bias+relu, 3 *0.125
template<int EPI, bool OUT_PLANES>
__global__ __launch_bounds__(256) void mma_gemm_kernel(
    const __nv_bfloat16* __restrict__ Ahi, const __nv_bfloat16* __restrict__ Alo,
    long lda, long sA1, long sA2,
    const __nv_bfloat16* __restrict__ Bhi, const __nv_bfloat16* __restrict__ Blo,
    long ldb, long sB1, long sB2,
    const float* __restrict__ bias,
    float* __restrict__ Cf,
    __nv_bfloat16* __restrict__ Chi, __nv_bfloat16* __restrict__ Clo,
    long ldc, long sC1, long sC2,
    int K)
{
    __shared__ __align__(16) char sm[49152];
    // layout: Ahi 0..16K, Alo 16K..32K, Bhi 32K..40K, Blo 40K..48K
    const uint32_t smb = smem_to_u32(sm);

    const int tid = threadIdx.x;
    const int lane = tid & 31;
    const int wid = tid >> 5;
    const int wr = wid >> 1;          // warp row 0..3
    const int wc = wid & 1;           // warp col 0..1
    const int m0 = wr * 32;
    const int n0w = wc * 32;

    const int z = blockIdx.z;
    const long offA = (long)(z >> 3) * sA1 + (long)(z & 7) * sA2;
    const long offB = (long)(z >> 3) * sB1 + (long)(z & 7) * sB2;
    const long offC = (long)(z >> 3) * sC1 + (long)(z & 7) * sC2;
    const int row0 = blockIdx.y * 128;
    const int col0 = blockIdx.x * 64;

    const __nv_bfloat16* ah = Ahi + offA;
    const __nv_bfloat16* al = Alo + offA;
    const __nv_bfloat16* bhp = Bhi + offB;
    const __nv_bfloat16* blp = Blo + offB;

    float acc[2][4][4] = {};

    // precomputed ldmatrix shared addresses (constant across chunks, vary by ks)
    const int aRow = m0 + (lane & 15);
    const int aColOff = (lane >> 4) << 4;                        // 0 or 16 bytes
    const int bRow0 = n0w + (lane & 7) + ((lane >> 4) & 1) * 8;  // within 16-row pair group
    const int bColOff = ((lane >> 3) & 1) << 4;

    const int nchunks = K >> 6;
    for (int chunk = 0; chunk < nchunks; chunk++) {
        const int c0k = chunk << 6;
        // ---- stage A (128x64 bf16 per plane) ----
        #pragma unroll
        for (int t = 0; t < 4; t++) {
            int i = tid + t * 256;           // 0..1023
            int r = i >> 3, seg = i & 7;
            size_t src = (size_t)(row0 + r) * lda + c0k + seg * 8;
            uint32_t off = SWZ((uint32_t)(r * 128 + seg * 16));
            *(float4*)(sm + off)         = *(const float4*)(ah + src);
            *(float4*)(sm + 16384 + off) = *(const float4*)(al + src);
        }
        // ---- stage B (64x64 bf16 per plane) ----
        #pragma unroll
        for (int t = 0; t < 2; t++) {
            int i = tid + t * 256;           // 0..511
            int r = i >> 3, seg = i & 7;
            size_t src = (size_t)(col0 + r) * ldb + c0k + seg * 8;
            uint32_t off = SWZ((uint32_t)(r * 128 + seg * 16));
            *(float4*)(sm + 32768 + off) = *(const float4*)(bhp + src);
            *(float4*)(sm + 40960 + off) = *(const float4*)(blp + src);
        }
        __syncthreads();

        #pragma unroll
        for (int ks = 0; ks < 4; ks++) {
            const int kb = ks * 32;   // byte offset of this k16 step
            uint32_t a_hi[2][4], a_lo[2][4], b_hi[2][4], b_lo[2][4];
            #pragma unroll
            for (int mt = 0; mt < 2; mt++) {
                uint32_t off = SWZ((uint32_t)((aRow + mt * 16) * 128 + kb + aColOff));
                LDMATRIX_X4(a_hi[mt], smb + off);
                LDMATRIX_X4(a_lo[mt], smb + 16384 + off);
            }
            #pragma unroll
            for (int np = 0; np < 2; np++) {
                uint32_t off = SWZ((uint32_t)((bRow0 + np * 16) * 128 + kb + bColOff));
                LDMATRIX_X4(b_hi[np], smb + 32768 + off);
                LDMATRIX_X4(b_lo[np], smb + 40960 + off);
            }
            #pragma unroll
            for (int mt = 0; mt < 2; mt++)
                #pragma unroll
                for (int nt = 0; nt < 4; nt++) {
                    const int np = nt >> 1, hb = (nt & 1) * 2;
                    MMA_BF16(acc[mt][nt], a_hi[mt], b_hi[np][hb], b_hi[np][hb + 1]);
                    MMA_BF16(acc[mt][nt], a_hi[mt], b_lo[np][hb], b_lo[np][hb + 1]);
                    MMA_BF16(acc[mt][nt], a_lo[mt], b_hi[np][hb], b_hi[np][hb + 1]);
                }
        }
        __syncthreads();
    }

    // ---- epilogue ----
    #pragma unroll
    for (int mt = 0; mt < 2; mt++)
        #pragma unroll
        for (int nt = 0; nt < 4; nt++) {
            const long rbase = row0 + m0 + mt * 16 + (lane >> 2);
            const long col = col0 + n0w + nt * 8 + (lane & 3) * 2;
            float b0f = 0.f, b1f = 0.f;
            if (EPI == 1 || EPI == 2) { b0f = bias[col]; b1f = bias[col + 1]; }
            #pragma unroll
            for (int half = 0; half < 2; half++) {
                const long r = rbase + half * 8;
                float v0 = acc[mt][nt][half * 2 + 0];
                float v1 = acc[mt][nt][half * 2 + 1];
                if (EPI == 1 || EPI == 2) { v0 += b0f; v1 += b1f; }
                if (EPI == 2) { v0 = fmaxf(v0, 0.f); v1 = fmaxf(v1, 0.f); }
                if (EPI == 3) { v0 *= 0.125f; v1 *= 0.125f; }
                const size_t dst = (size_t)(offC + r * ldc + col);
                if (Cf) *(float2*)(Cf + dst) = make_float2(v0, v1);
                if (OUT_PLANES) {
                    __nv_bfloat16 h0, l0, h1, l1;
                    split_bf16(v0, h0, l0);
                    split_bf16(v1, h1, l1);
                    *(__nv_bfloat162*)(Chi + dst) = __nv_bfloat162(h0, h1);
                    *(__nv_bfloat162*)(Clo + dst) = __nv_bfloat162(l0, l1);
                }
            }
        }
}

// ===================== softmax: fp32 scores in, bf16 hi/lo P out =====================
__global__ void softmax_kernel(const float* __restrict__ sc,
                               __nv_bfloat16* __restrict__ phi,
                               __nv_bfloat16* __restrict__ plo)
{
    __shared__ float red[256];
    const size_t rowoff = (size_t)blockIdx.x * SS;
    const float* p = sc + rowoff;
    const int t = threadIdx.x;

    float vals[8];
    float m = -1e30f;
    #pragma unroll
    for (int i = 0; i < 8; i++) { vals[i] = p[t + i * 256]; m = fmaxf(m, vals[i]); }
    red[t] = m; __syncthreads();
    for (int s = 128; s > 0; s >>= 1) {
        if (t < s) red[t] = fmaxf(red[t], red[t + s]);
        __syncthreads();
    }
    m = red[0]; __syncthreads();

    float sum = 0.0f;
    #pragma unroll
    for (int i = 0; i < 8; i++) { vals[i] = __expf(vals[i] - m); sum += vals[i]; }
    red[t] = sum; __syncthreads();
    for (int s = 128; s > 0; s >>= 1) {
        if (t < s) red[t] += red[t + s];
        __syncthreads();
    }
    float inv = 1.0f / red[0];
    #pragma unroll
    for (int i = 0; i < 8; i++) {
        float pv = vals[i] * inv;
        __nv_bfloat16 h, l; split_bf16(pv, h, l);
        phi[rowoff + t + i * 256] = h;
        plo[rowoff + t + i * 256] = l;
    }
}

// ===================== add + LayerNorm =====================
template<bool PLANES>
__global__ void add_ln_kernel(const float* __restrict__ xa, const float* __restrict__ xb,
                              const float* __restrict__ g, const float* __restrict__ be,
                              float* __restrict__ out,
                              __nv_bfloat16* __restrict__ ohi, __nv_bfloat16* __restrict__ olo)
{
    __shared__ float red[256];
    const int row = blockIdx.x;
    const int t = threadIdx.x;
    const float* pa = xa + (size_t)row * DM;
    const float* pb = xb + (size_t)row * DM;

    float v0 = pa[t] + pb[t];
    float v1 = pa[t + 256] + pb[t + 256];

    red[t] = v0 + v1; __syncthreads();
    for (int s = 128; s > 0; s >>= 1) {
        if (t < s) red[t] += red[t + s];
        __syncthreads();
    }
    float mu = red[0] * (1.0f / DM); __syncthreads();

    float d0 = v0 - mu, d1 = v1 - mu;
    red[t] = d0 * d0 + d1 * d1; __syncthreads();
    for (int s = 128; s > 0; s >>= 1) {
        if (t < s) red[t] += red[t + s];
        __syncthreads();
    }
    float r = rsqrtf(red[0] * (1.0f / DM) + 1e-5f);

    float o0 = d0 * r * g[t] + be[t];
    float o1 = d1 * r * g[t + 256] + be[t + 256];
    out[(size_t)row * DM + t] = o0;
    out[(size_t)row * DM + t + 256] = o1;
    if (PLANES) {
        __nv_bfloat16 h, l;
        split_bf16(o0, h, l); ohi[(size_t)row * DM + t] = h;       olo[(size_t)row * DM + t] = l;
        split_bf16(o1, h, l); ohi[(size_t)row * DM + t + 256] = h; olo[(size_t)row * DM + t + 256] = l;
    }
}

// ===================== launch =====================
extern "C" void kernel_launch(void* const* d_in, const int* in_sizes, int n_in,
                              void* d_out, int out_size)
{
    const float* x   = (const float*)d_in[0];
    const float* Wq  = (const float*)d_in[1];
    const float* bq  = (const float*)d_in[2];
    const float* Wk  = (const float*)d_in[3];
    const float* bk  = (const float*)d_in[4];
    const float* Wv  = (const float*)d_in[5];
    const float* bv  = (const float*)d_in[6];
    const float* Wo  = (const float*)d_in[7];
    const float* bo  = (const float*)d_in[8];
    const float* W1  = (const float*)d_in[9];
    const float* b1  = (const float*)d_in[10];
    const float* W2  = (const float*)d_in[11];
    const float* b2  = (const float*)d_in[12];
    const float* g1  = (const float*)d_in[13];
    const float* be1 = (const float*)d_in[14];
    const float* g2  = (const float*)d_in[15];
    const float* be2 = (const float*)d_in[16];

    #define SYM(p, s) cudaGetSymbolAddress((void**)&p, s)
    float *sc, *ao, *hbuf, *ff2;
    __nv_bfloat16 *xh,*xl,*qh,*ql,*kh,*kl,*vh,*vl,*vth,*vtl,*ch,*cl,*hh,*hl,*f1h,*f1l,*ph,*pl;
    __nv_bfloat16 *wqh,*wql,*wkh,*wkl,*wvh,*wvl,*woh,*wol,*w1h,*w1l,*w2h,*w2l;
    SYM(sc, g_sc); SYM(ao, g_ao); SYM(hbuf, g_h); SYM(ff2, g_ff2);
    SYM(xh, g_x_hi); SYM(xl, g_x_lo);
    SYM(qh, g_q_hi); SYM(ql, g_q_lo);
    SYM(kh, g_k_hi); SYM(kl, g_k_lo);
    SYM(vh, g_v_hi); SYM(vl, g_v_lo);
    SYM(vth, g_vt_hi); SYM(vtl, g_vt_lo);
    SYM(ch, g_ctx_hi); SYM(cl, g_ctx_lo);
    SYM(hh, g_h_hi); SYM(hl, g_h_lo);
    SYM(f1h, g_f1_hi); SYM(f1l, g_f1_lo);
    SYM(ph, g_p_hi); SYM(pl, g_p_lo);
    SYM(wqh, g_wq_hi); SYM(wql, g_wq_lo);
    SYM(wkh, g_wk_hi); SYM(wkl, g_wk_lo);
    SYM(wvh, g_wv_hi); SYM(wvl, g_wv_lo);
    SYM(woh, g_wo_hi); SYM(wol, g_wo_lo);
    SYM(w1h, g_w1_hi); SYM(w1l, g_w1_lo);
    SYM(w2h, g_w2_hi); SYM(w2l, g_w2_lo);
    #undef SYM

    // 1. convert activations + weights
    cvt_kernel<<<(NT * DM + 255) / 256, 256>>>(x, xh, xl, NT * DM);
    wtrans_kernel<<<dim3(DM / 32, DM / 32), 256>>>(Wq, DM, DM, wqh, wql);
    wtrans_kernel<<<dim3(DM / 32, DM / 32), 256>>>(Wk, DM, DM, wkh, wkl);
    wtrans_kernel<<<dim3(DM / 32, DM / 32), 256>>>(Wv, DM, DM, wvh, wvl);
    wtrans_kernel<<<dim3(DM / 32, DM / 32), 256>>>(Wo, DM, DM, woh, wol);
    wtrans_kernel<<<dim3(DFF / 32, DM / 32), 256>>>(W1, DM, DFF, w1h, w1l);
    wtrans_kernel<<<dim3(DM / 32, DFF / 32), 256>>>(W2, DFF, DM, w2h, w2l);

    // 2. QKV projections
    mma_gemm_kernel<1, true><<<dim3(DM / 64, NT / 128, 1), 256>>>(
        xh, xl, DM, 0, 0, wqh, wql, DM, 0, 0, bq,
        nullptr, qh, ql, DM, 0, 0, DM);
    mma_gemm_kernel<1, true><<<dim3(DM / 64, NT / 128, 1), 256>>>(
        xh, xl, DM, 0, 0, wkh, wkl, DM, 0, 0, bk,
        nullptr, kh, kl, DM, 0, 0, DM);
    mma_gemm_kernel<1, true><<<dim3(DM / 64, NT / 128, 1), 256>>>(
        xh, xl, DM, 0, 0, wvh, wvl, DM, 0, 0, bv,
        nullptr, vh, vl, DM, 0, 0, DM);

    // 3. transpose V per head
    vtrans_kernel<<<dim3(SS / 64, BH), 256>>>(vh, vl, vth, vtl);

    // 4. scores = Q @ K^T * 0.125 (fp32)
    mma_gemm_kernel<3, false><<<dim3(SS / 64, SS / 128, BH), 256>>>(
        qh, ql, DM, (long)SS * DM, 64,
        kh, kl, DM, (long)SS * DM, 64,
        nullptr,
        sc, nullptr, nullptr, SS, 8L * SS * SS, (long)SS * SS, HD);

    // 5. softmax -> P planes
    softmax_kernel<<<BH * SS, 256>>>(sc, ph, pl);

    // 6. ctx = P @ V^T (B = vT [bh][d][s])
    mma_gemm_kernel<0, true><<<dim3(1, SS / 128, BH), 256>>>(
        ph, pl, SS, 8L * SS * SS, (long)SS * SS,
        vth, vtl, SS, 8L * 64 * SS, 64L * SS,
        nullptr,
        nullptr, ch, cl, DM, (long)SS * DM, 64, SS);

    // 7. attn_out = ctx @ Wo + bo (fp32)
    mma_gemm_kernel<1, false><<<dim3(DM / 64, NT / 128, 1), 256>>>(
        ch, cl, DM, 0, 0, woh, wol, DM, 0, 0, bo,
        ao, nullptr, nullptr, DM, 0, 0, DM);

    // 8. h = LN(x + ao)
    add_ln_kernel<true><<<NT, 256>>>(x, ao, g1, be1, hbuf, hh, hl);

    // 9. ff1 = relu(h @ W1 + b1)
    mma_gemm_kernel<2, true><<<dim3(DFF / 64, NT / 128, 1), 256>>>(
        hh, hl, DM, 0, 0, w1h, w1l, DM, 0, 0, b1,
        nullptr, f1h, f1l, DFF, 0, 0, DM);

    // 10. ff2 = ff1 @ W2 + b2 (fp32)
    mma_gemm_kernel<1, false><<<dim3(DM / 64, NT / 128, 1), 256>>>(
        f1h, f1l, DFF, 0, 0, w2h, w2l, DFF, 0, 0, b2,
        ff2, nullptr, nullptr, DM, 0, 0, DFF);

    // 11. out = LN(h + ff2)
    add_ln_kernel<false><<<NT, 256>>>(hbuf, ff2, g2, be2, (float*)d_out, nullptr, nullptr);
}

// round 4
// speedup vs baseline: 3.8324x; 1.4096x over previous
#include <cuda_runtime.h>
#include <cuda_bf16.h>
#include <cstdint>
#include <math.h>

#define DM 512
#define NH 8
#define HD 64
#define DFF 2048
#define BB 2
#define SS 2048
#define NT (BB*SS)
#define BH (BB*NH)

#define SWZ(off) ((off) ^ (((off) >> 3) & 0x70))

__device__ __forceinline__ uint32_t smem_to_u32(const void* smem_ptr) {
    uint32_t addr;
    asm("{ .reg .u64 tmp; cvta.to.shared.u64 tmp, %1; cvt.u32.u64 %0, tmp; }"
        : "=r"(addr) : "l"(smem_ptr));
    return addr;
}

#define LDMATRIX_X4(r, addr) \
    asm volatile("ldmatrix.sync.aligned.m8n8.x4.shared.b16 {%0,%1,%2,%3}, [%4];" \
        : "=r"((r)[0]), "=r"((r)[1]), "=r"((r)[2]), "=r"((r)[3]) : "r"(addr))

#define MMA_BF16(c, a, b0, b1) \
    asm volatile("mma.sync.aligned.m16n8k16.row.col.f32.bf16.bf16.f32 " \
        "{%0,%1,%2,%3}, {%4,%5,%6,%7}, {%8,%9}, {%0,%1,%2,%3};" \
        : "+f"((c)[0]), "+f"((c)[1]), "+f"((c)[2]), "+f"((c)[3]) \
        : "r"((a)[0]), "r"((a)[1]), "r"((a)[2]), "r"((a)[3]), "r"(b0), "r"(b1))

#define CP_ASYNC16(dst, src) \
    asm volatile("cp.async.cg.shared.global [%0], [%1], 16;" :: "r"(dst), "l"(src))
#define CP_COMMIT() asm volatile("cp.async.commit_group;" ::: "memory")
#define CP_WAIT(n)  asm volatile("cp.async.wait_group %0;" :: "n"(n) : "memory")

// ===================== static device scratch =====================
__device__ __nv_bfloat16 g_x_hi[NT * DM],  g_x_lo[NT * DM];
__device__ __nv_bfloat16 g_q_hi[NT * DM],  g_q_lo[NT * DM];
__device__ __nv_bfloat16 g_k_hi[NT * DM],  g_k_lo[NT * DM];
__device__ __nv_bfloat16 g_v_hi[NT * DM],  g_v_lo[NT * DM];
__device__ __nv_bfloat16 g_vt_hi[NT * DM], g_vt_lo[NT * DM];   // [bh][d][s]
__device__ __nv_bfloat16 g_ctx_hi[NT * DM], g_ctx_lo[NT * DM];
__device__ __nv_bfloat16 g_h_hi[NT * DM],  g_h_lo[NT * DM];
__device__ __nv_bfloat16 g_f1_hi[NT * DFF], g_f1_lo[NT * DFF];

__device__ __nv_bfloat16 g_wq_hi[DM * DM], g_wq_lo[DM * DM];   // [N,K]
__device__ __nv_bfloat16 g_wk_hi[DM * DM], g_wk_lo[DM * DM];
__device__ __nv_bfloat16 g_wv_hi[DM * DM], g_wv_lo[DM * DM];
__device__ __nv_bfloat16 g_wo_hi[DM * DM], g_wo_lo[DM * DM];
__device__ __nv_bfloat16 g_w1_hi[DM * DFF], g_w1_lo[DM * DFF];
__device__ __nv_bfloat16 g_w2_hi[DM * DFF], g_w2_lo[DM * DFF];

__device__ float g_ao[NT * DM];
__device__ float g_h[NT * DM];
__device__ float g_ff2[NT * DM];

// ===================== helpers =====================
__device__ __forceinline__ void split_bf16(float x, __nv_bfloat16& h, __nv_bfloat16& l) {
    h = __float2bfloat16(x);
    l = __float2bfloat16(x - __bfloat162float(h));
}
__device__ __forceinline__ void pack_split2(float x, float y, uint32_t& hi, uint32_t& lo) {
    __nv_bfloat16 hx, lx, hy, ly;
    split_bf16(x, hx, lx);
    split_bf16(y, hy, ly);
    __nv_bfloat162 H(hx, hy), L(lx, ly);
    hi = *(uint32_t*)&H;
    lo = *(uint32_t*)&L;
}

__global__ void cvt_kernel(const float* __restrict__ in,
                           __nv_bfloat16* __restrict__ hi,
                           __nv_bfloat16* __restrict__ lo, int n)
{
    int i = blockIdx.x * 256 + threadIdx.x;
    if (i < n) { __nv_bfloat16 h, l; split_bf16(in[i], h, l); hi[i] = h; lo[i] = l; }
}

// W[K,N] fp32 -> WT[N,K] hi/lo bf16
__global__ void wtrans_kernel(const float* __restrict__ W, int K, int N,
                              __nv_bfloat16* __restrict__ Thi,
                              __nv_bfloat16* __restrict__ Tlo)
{
    __shared__ float tile[32][33];
    int n0 = blockIdx.x * 32, k0 = blockIdx.y * 32;
    int tx = threadIdx.x & 31, ty = threadIdx.x >> 5;
    #pragma unroll
    for (int i = 0; i < 32; i += 8)
        tile[ty + i][tx] = W[(size_t)(k0 + ty + i) * N + n0 + tx];
    __syncthreads();
    #pragma unroll
    for (int i = 0; i < 32; i += 8) {
        float v = tile[tx][ty + i];
        __nv_bfloat16 h, l; split_bf16(v, h, l);
        size_t dst = (size_t)(n0 + ty + i) * K + k0 + tx;
        Thi[dst] = h; Tlo[dst] = l;
    }
}

// v planes [token, h*64+d] -> vT planes [bh][d][s]
__global__ void vtrans_kernel(const __nv_bfloat16* __restrict__ vh,
                              const __nv_bfloat16* __restrict__ vl,
                              __nv_bfloat16* __restrict__ oth,
                              __nv_bfloat16* __restrict__ otl)
{
    __shared__ unsigned short th[64][65];
    __shared__ unsigned short tl[64][65];
    int bh = blockIdx.y; int b = bh >> 3, h = bh & 7;
    int s0 = blockIdx.x * 64;
    for (int i = threadIdx.x; i < 64 * 64; i += 256) {
        int r = i >> 6, c = i & 63;
        size_t src = (size_t)(b * SS + s0 + r) * DM + h * 64 + c;
        th[r][c] = ((const unsigned short*)vh)[src];
        tl[r][c] = ((const unsigned short*)vl)[src];
    }
    __syncthreads();
    for (int i = threadIdx.x; i < 64 * 64; i += 256) {
        int d = i >> 6, s = i & 63;
        size_t dst = ((size_t)bh * 64 + d) * SS + s0 + s;
        ((unsigned short*)oth)[dst] = th[s][d];
        ((unsigned short*)otl)[dst] = tl[s][d];
    }
}

// ===================== split-bf16 mma.sync GEMM (unchanged engine) =====================
template<int EPI, bool OUT_PLANES>
__global__ __launch_bounds__(256) void mma_gemm_kernel(
    const __nv_bfloat16* __restrict__ Ahi, const __nv_bfloat16* __restrict__ Alo,
    long lda,
    const __nv_bfloat16* __restrict__ Bhi, const __nv_bfloat16* __restrict__ Blo,
    long ldb,
    const float* __restrict__ bias,
    float* __restrict__ Cf,
    __nv_bfloat16* __restrict__ Chi, __nv_bfloat16* __restrict__ Clo,
    long ldc,
    int K)
{
    __shared__ __align__(16) char sm[49152];
    const uint32_t smb = smem_to_u32(sm);

    const int tid = threadIdx.x;
    const int lane = tid & 31;
    const int wid = tid >> 5;
    const int wr = wid >> 1;
    const int wc = wid & 1;
    const int m0 = wr * 32;
    const int n0w = wc * 32;

    const int row0 = blockIdx.y * 128;
    const int col0 = blockIdx.x * 64;

    float acc[2][4][4] = {};

    const int aRow = m0 + (lane & 15);
    const int aColOff = (lane >> 4) << 4;
    const int bRow0 = n0w + (lane & 7) + ((lane >> 4) & 1) * 8;
    const int bColOff = ((lane >> 3) & 1) << 4;

    const int nchunks = K >> 6;
    for (int chunk = 0; chunk < nchunks; chunk++) {
        const int c0k = chunk << 6;
        #pragma unroll
        for (int t = 0; t < 4; t++) {
            int i = tid + t * 256;
            int r = i >> 3, seg = i & 7;
            size_t src = (size_t)(row0 + r) * lda + c0k + seg * 8;
            uint32_t off = SWZ((uint32_t)(r * 128 + seg * 16));
            *(float4*)(sm + off)         = *(const float4*)(Ahi + src);
            *(float4*)(sm + 16384 + off) = *(const float4*)(Alo + src);
        }
        #pragma unroll
        for (int t = 0; t < 2; t++) {
            int i = tid + t * 256;
            int r = i >> 3, seg = i & 7;
            size_t src = (size_t)(col0 + r) * ldb + c0k + seg * 8;
            uint32_t off = SWZ((uint32_t)(r * 128 + seg * 16));
            *(float4*)(sm + 32768 + off) = *(const float4*)(Bhi + src);
            *(float4*)(sm + 40960 + off) = *(const float4*)(Blo + src);
        }
        __syncthreads();

        #pragma unroll
        for (int ks = 0; ks < 4; ks++) {
            const int kb = ks * 32;
            uint32_t a_hi[2][4], a_lo[2][4], b_hi[2][4], b_lo[2][4];
            #pragma unroll
            for (int mt = 0; mt < 2; mt++) {
                uint32_t off = SWZ((uint32_t)((aRow + mt * 16) * 128 + kb + aColOff));
                LDMATRIX_X4(a_hi[mt], smb + off);
                LDMATRIX_X4(a_lo[mt], smb + 16384 + off);
            }
            #pragma unroll
            for (int np = 0; np < 2; np++) {
                uint32_t off = SWZ((uint32_t)((bRow0 + np * 16) * 128 + kb + bColOff));
                LDMATRIX_X4(b_hi[np], smb + 32768 + off);
                LDMATRIX_X4(b_lo[np], smb + 40960 + off);
            }
            #pragma unroll
            for (int mt = 0; mt < 2; mt++)
                #pragma unroll
                for (int nt = 0; nt < 4; nt++) {
                    const int np = nt >> 1, hb = (nt & 1) * 2;
                    MMA_BF16(acc[mt][nt], a_hi[mt], b_hi[np][hb], b_hi[np][hb + 1]);
                    MMA_BF16(acc[mt][nt], a_hi[mt], b_lo[np][hb], b_lo[np][hb + 1]);
                    MMA_BF16(acc[mt][nt], a_lo[mt], b_hi[np][hb], b_hi[np][hb + 1]);
                }
        }
        __syncthreads();
    }

    #pragma unroll
    for (int mt = 0; mt < 2; mt++)
        #pragma unroll
        for (int nt = 0; nt < 4; nt++) {
            const long rbase = row0 + m0 + mt * 16 + (lane >> 2);
            const long col = col0 + n0w + nt * 8 + (lane & 3) * 2;
            float b0f = 0.f, b1f = 0.f;
            if (EPI == 1 || EPI == 2) { b0f = bias[col]; b1f = bias[col + 1]; }
            #pragma unroll
            for (int half = 0; half < 2; half++) {
                const long r = rbase + half * 8;
                float v0 = acc[mt][nt][half * 2 + 0];
                float v1 = acc[mt][nt][half * 2 + 1];
                if (EPI == 1 || EPI == 2) { v0 += b0f; v1 += b1f; }
                if (EPI == 2) { v0 = fmaxf(v0, 0.f); v1 = fmaxf(v1, 0.f); }
                const size_t dst = (size_t)(r * ldc + col);
                if (Cf) *(float2*)(Cf + dst) = make_float2(v0, v1);
                if (OUT_PLANES) {
                    uint32_t hi, lo;
                    pack_split2(v0, v1, hi, lo);
                    *(uint32_t*)(Chi + dst) = hi;
                    *(uint32_t*)(Clo + dst) = lo;
                }
            }
        }
}

// ===================== fused flash attention =====================
// grid (SS/128, BH), 256 threads = 8 warps; warp w owns rows [w*16, w*16+16).
// smem: double-buffered K/V tiles: buf*32768 + {KH:0, KL:8192, VH:16384, VL:24576}
__global__ __launch_bounds__(256) void flash_attn_kernel(
    const __nv_bfloat16* __restrict__ qh_, const __nv_bfloat16* __restrict__ ql_,
    const __nv_bfloat16* __restrict__ kh_, const __nv_bfloat16* __restrict__ kl_,
    const __nv_bfloat16* __restrict__ vth_, const __nv_bfloat16* __restrict__ vtl_,
    __nv_bfloat16* __restrict__ ch_, __nv_bfloat16* __restrict__ cl_)
{
    extern __shared__ __align__(16) char sm[];
    const uint32_t smb = smem_to_u32(sm);
    const int tid = threadIdx.x, lane = tid & 31, wid = tid >> 5;
    const int bh = blockIdx.y;
    const int b = bh >> 3, h = bh & 7;
    const int q0 = blockIdx.x * 128;

    const __nv_bfloat16* qhp = qh_ + (size_t)(b * SS + q0) * DM + h * 64;
    const __nv_bfloat16* qlp = ql_ + (size_t)(b * SS + q0) * DM + h * 64;
    const __nv_bfloat16* khp = kh_ + (size_t)b * SS * DM + h * 64;
    const __nv_bfloat16* klp = kl_ + (size_t)b * SS * DM + h * 64;
    const __nv_bfloat16* vthp = vth_ + (size_t)bh * 64 * SS;
    const __nv_bfloat16* vtlp = vtl_ + (size_t)bh * 64 * SS;

    // ---- stage Q into smem (reusing buffer area), grab fragments ----
    #pragma unroll
    for (int t = 0; t < 4; t++) {
        int i = tid + t * 256;          // 0..1023
        int r = i >> 3, seg = i & 7;
        uint32_t off = SWZ((uint32_t)(r * 128 + seg * 16));
        *(float4*)(sm + off)         = *(const float4*)(qhp + (size_t)r * DM + seg * 8);
        *(float4*)(sm + 16384 + off) = *(const float4*)(qlp + (size_t)r * DM + seg * 8);
    }
    __syncthreads();
    uint32_t qfh[4][4], qfl[4][4];
    {
        const int aRow = wid * 16 + (lane & 15);
        const int aCol = (lane >> 4) << 4;
        #pragma unroll
        for (int ks = 0; ks < 4; ks++) {
            uint32_t off = SWZ((uint32_t)(aRow * 128 + ks * 32 + aCol));
            LDMATRIX_X4(qfh[ks], smb + off);
            LDMATRIX_X4(qfl[ks], smb + 16384 + off);
        }
    }
    __syncthreads();

    // B-fragment lane addressing constants (shared by K and VT tiles)
    const int bRow = (lane & 7) + ((lane >> 4) & 1) * 8;
    const int bCol = ((lane >> 3) & 1) << 4;

    float acc_o[8][4] = {};
    float m0r = -1e30f, m1r = -1e30f, l0 = 0.f, l1 = 0.f;

    // tile loader: 4 planes x 64 rows x 128B, cp.async
    auto load_tile = [&](int it, int buf) {
        const int kv0 = it * 64;
        const uint32_t base = smb + buf * 32768;
        #pragma unroll
        for (int t = 0; t < 8; t++) {
            int i = tid + t * 256;       // 0..2047
            int plane = i >> 9;
            int r = (i >> 3) & 63;
            int seg = i & 7;
            uint32_t dst = base + plane * 8192 + SWZ((uint32_t)(r * 128 + seg * 16));
            const __nv_bfloat16* src;
            if (plane == 0)      src = khp  + (size_t)(kv0 + r) * DM + seg * 8;
            else if (plane == 1) src = klp  + (size_t)(kv0 + r) * DM + seg * 8;
            else if (plane == 2) src = vthp + (size_t)r * SS + kv0 + seg * 8;
            else                 src = vtlp + (size_t)r * SS + kv0 + seg * 8;
            CP_ASYNC16(dst, src);
        }
        CP_COMMIT();
    };

    load_tile(0, 0);

    const int NIT = SS / 64;
    for (int it = 0; it < NIT; it++) {
        const int buf = it & 1;
        if (it + 1 < NIT) { load_tile(it + 1, buf ^ 1); CP_WAIT(1); }
        else               { CP_WAIT(0); }
        __syncthreads();

        const uint32_t kbase = smb + buf * 32768;
        const uint32_t vbase = kbase + 16384;

        // ---- S = Q @ K^T (3-pass split) ----
        float s[8][4] = {};
        #pragma unroll
        for (int ks = 0; ks < 4; ks++) {
            uint32_t bhf[4][4], blf[4][4];
            #pragma unroll
            for (int np = 0; np < 4; np++) {
                uint32_t off = SWZ((uint32_t)((np * 16 + bRow) * 128 + ks * 32 + bCol));
                LDMATRIX_X4(bhf[np], kbase + off);
                LDMATRIX_X4(blf[np], kbase + 8192 + off);
            }
            #pragma unroll
            for (int nt = 0; nt < 8; nt++) {
                const int np = nt >> 1, hb = (nt & 1) * 2;
                MMA_BF16(s[nt], qfh[ks], bhf[np][hb], bhf[np][hb + 1]);
                MMA_BF16(s[nt], qfh[ks], blf[np][hb], blf[np][hb + 1]);
                MMA_BF16(s[nt], qfl[ks], bhf[np][hb], bhf[np][hb + 1]);
            }
        }

        // ---- online softmax (scale 0.125 folded into exp) ----
        float mx0 = -1e30f, mx1 = -1e30f;
        #pragma unroll
        for (int t = 0; t < 8; t++) {
            mx0 = fmaxf(mx0, fmaxf(s[t][0], s[t][1]));
            mx1 = fmaxf(mx1, fmaxf(s[t][2], s[t][3]));
        }
        mx0 = fmaxf(mx0, __shfl_xor_sync(0xffffffffu, mx0, 1));
        mx0 = fmaxf(mx0, __shfl_xor_sync(0xffffffffu, mx0, 2));
        mx1 = fmaxf(mx1, __shfl_xor_sync(0xffffffffu, mx1, 1));
        mx1 = fmaxf(mx1, __shfl_xor_sync(0xffffffffu, mx1, 2));

        const float mn0 = fmaxf(m0r, 0.125f * mx0);
        const float mn1 = fmaxf(m1r, 0.125f * mx1);
        const float alpha0 = __expf(m0r - mn0);
        const float alpha1 = __expf(m1r - mn1);
        m0r = mn0; m1r = mn1;

        float sum0 = 0.f, sum1 = 0.f;
        #pragma unroll
        for (int t = 0; t < 8; t++) {
            float p0 = __expf(fmaf(0.125f, s[t][0], -mn0));
            float p1 = __expf(fmaf(0.125f, s[t][1], -mn0));
            float p2 = __expf(fmaf(0.125f, s[t][2], -mn1));
            float p3 = __expf(fmaf(0.125f, s[t][3], -mn1));
            sum0 += p0 + p1; sum1 += p2 + p3;
            s[t][0] = p0; s[t][1] = p1; s[t][2] = p2; s[t][3] = p3;
        }
        sum0 += __shfl_xor_sync(0xffffffffu, sum0, 1);
        sum0 += __shfl_xor_sync(0xffffffffu, sum0, 2);
        sum1 += __shfl_xor_sync(0xffffffffu, sum1, 1);
        sum1 += __shfl_xor_sync(0xffffffffu, sum1, 2);
        l0 = l0 * alpha0 + sum0;
        l1 = l1 * alpha1 + sum1;
        #pragma unroll
        for (int t = 0; t < 8; t++) {
            acc_o[t][0] *= alpha0; acc_o[t][1] *= alpha0;
            acc_o[t][2] *= alpha1; acc_o[t][3] *= alpha1;
        }

        // ---- O += P @ V (P from registers, 3-pass split) ----
        #pragma unroll
        for (int j = 0; j < 4; j++) {
            uint32_t pa_h[4], pa_l[4];
            pack_split2(s[2*j][0],   s[2*j][1],   pa_h[0], pa_l[0]);
            pack_split2(s[2*j][2],   s[2*j][3],   pa_h[1], pa_l[1]);
            pack_split2(s[2*j+1][0], s[2*j+1][1], pa_h[2], pa_l[2]);
            pack_split2(s[2*j+1][2], s[2*j+1][3], pa_h[3], pa_l[3]);

            uint32_t vhf[4][4], vlf[4][4];
            #pragma unroll
            for (int np = 0; np < 4; np++) {
                uint32_t off = SWZ((uint32_t)((np * 16 + bRow) * 128 + j * 32 + bCol));
                LDMATRIX_X4(vhf[np], vbase + off);
                LDMATRIX_X4(vlf[np], vbase + 8192 + off);
            }
            #pragma unroll
            for (int nt = 0; nt < 8; nt++) {
                const int np = nt >> 1, hb = (nt & 1) * 2;
                MMA_BF16(acc_o[nt], pa_h, vhf[np][hb], vhf[np][hb + 1]);
                MMA_BF16(acc_o[nt], pa_h, vlf[np][hb], vlf[np][hb + 1]);
                MMA_BF16(acc_o[nt], pa_l, vhf[np][hb], vhf[np][hb + 1]);
            }
        }
        __syncthreads();
    }

    // ---- epilogue: normalize + store ctx planes ----
    const float inv0 = 1.0f / l0;
    const float inv1 = 1.0f / l1;
    const size_t tok0 = (size_t)(b * SS + q0 + wid * 16 + (lane >> 2)) * DM + h * 64;
    #pragma unroll
    for (int t = 0; t < 8; t++) {
        const int dcol = t * 8 + (lane & 3) * 2;
        uint32_t hi, lo;
        pack_split2(acc_o[t][0] * inv0, acc_o[t][1] * inv0, hi, lo);
        *(uint32_t*)(ch_ + tok0 + dcol) = hi;
        *(uint32_t*)(cl_ + tok0 + dcol) = lo;
        pack_split2(acc_o[t][2] * inv1, acc_o[t][3] * inv1, hi, lo);
        *(uint32_t*)(ch_ + tok0 + 8 * DM + dcol) = hi;
        *(uint32_t*)(cl_ + tok0 + 8 * DM + dcol) = lo;
    }
}

// ===================== add + LayerNorm =====================
template<bool PLANES>
__global__ void add_ln_kernel(const float* __restrict__ xa, const float* __restrict__ xb,
                              const float* __restrict__ g, const float* __restrict__ be,
                              float* __restrict__ out,
                              __nv_bfloat16* __restrict__ ohi, __nv_bfloat16* __restrict__ olo)
{
    __shared__ float red[256];
    const int row = blockIdx.x;
    const int t = threadIdx.x;
    const float* pa = xa + (size_t)row * DM;
    const float* pb = xb + (size_t)row * DM;

    float v0 = pa[t] + pb[t];
    float v1 = pa[t + 256] + pb[t + 256];

    red[t] = v0 + v1; __syncthreads();
    for (int s = 128; s > 0; s >>= 1) {
        if (t < s) red[t] += red[t + s];
        __syncthreads();
    }
    float mu = red[0] * (1.0f / DM); __syncthreads();

    float d0 = v0 - mu, d1 = v1 - mu;
    red[t] = d0 * d0 + d1 * d1; __syncthreads();
    for (int s = 128; s > 0; s >>= 1) {
        if (t < s) red[t] += red[t + s];
        __syncthreads();
    }
    float r = rsqrtf(red[0] * (1.0f / DM) + 1e-5f);

    float o0 = d0 * r * g[t] + be[t];
    float o1 = d1 * r * g[t + 256] + be[t + 256];
    out[(size_t)row * DM + t] = o0;
    out[(size_t)row * DM + t + 256] = o1;
    if (PLANES) {
        __nv_bfloat16 h, l;
        split_bf16(o0, h, l); ohi[(size_t)row * DM + t] = h;       olo[(size_t)row * DM + t] = l;
        split_bf16(o1, h, l); ohi[(size_t)row * DM + t + 256] = h; olo[(size_t)row * DM + t + 256] = l;
    }
}

// ===================== launch =====================
extern "C" void kernel_launch(void* const* d_in, const int* in_sizes, int n_in,
                              void* d_out, int out_size)
{
    const float* x   = (const float*)d_in[0];
    const float* Wq  = (const float*)d_in[1];
    const float* bq  = (const float*)d_in[2];
    const float* Wk  = (const float*)d_in[3];
    const float* bk  = (const float*)d_in[4];
    const float* Wv  = (const float*)d_in[5];
    const float* bv  = (const float*)d_in[6];
    const float* Wo  = (const float*)d_in[7];
    const float* bo  = (const float*)d_in[8];
    const float* W1  = (const float*)d_in[9];
    const float* b1  = (const float*)d_in[10];
    const float* W2  = (const float*)d_in[11];
    const float* b2  = (const float*)d_in[12];
    const float* g1  = (const float*)d_in[13];
    const float* be1 = (const float*)d_in[14];
    const float* g2  = (const float*)d_in[15];
    const float* be2 = (const float*)d_in[16];

    #define SYM(p, s) cudaGetSymbolAddress((void**)&p, s)
    float *ao, *hbuf, *ff2;
    __nv_bfloat16 *xh,*xl,*qh,*ql,*kh,*kl,*vh,*vl,*vth,*vtl,*ch,*cl,*hh,*hl,*f1h,*f1l;
    __nv_bfloat16 *wqh,*wql,*wkh,*wkl,*wvh,*wvl,*woh,*wol,*w1h,*w1l,*w2h,*w2l;
    SYM(ao, g_ao); SYM(hbuf, g_h); SYM(ff2, g_ff2);
    SYM(xh, g_x_hi); SYM(xl, g_x_lo);
    SYM(qh, g_q_hi); SYM(ql, g_q_lo);
    SYM(kh, g_k_hi); SYM(kl, g_k_lo);
    SYM(vh, g_v_hi); SYM(vl, g_v_lo);
    SYM(vth, g_vt_hi); SYM(vtl, g_vt_lo);
    SYM(ch, g_ctx_hi); SYM(cl, g_ctx_lo);
    SYM(hh, g_h_hi); SYM(hl, g_h_lo);
    SYM(f1h, g_f1_hi); SYM(f1l, g_f1_lo);
    SYM(wqh, g_wq_hi); SYM(wql, g_wq_lo);
    SYM(wkh, g_wk_hi); SYM(wkl, g_wk_lo);
    SYM(wvh, g_wv_hi); SYM(wvl, g_wv_lo);
    SYM(woh, g_wo_hi); SYM(wol, g_wo_lo);
    SYM(w1h, g_w1_hi); SYM(w1l, g_w1_lo);
    SYM(w2h, g_w2_hi); SYM(w2l, g_w2_lo);
    #undef SYM

    cudaFuncSetAttribute(flash_attn_kernel,
                         cudaFuncAttributeMaxDynamicSharedMemorySize, 65536);

    // 1. convert activations + weights
    cvt_kernel<<<(NT * DM + 255) / 256, 256>>>(x, xh, xl, NT * DM);
    wtrans_kernel<<<dim3(DM / 32, DM / 32), 256>>>(Wq, DM, DM, wqh, wql);
    wtrans_kernel<<<dim3(DM / 32, DM / 32), 256>>>(Wk, DM, DM, wkh, wkl);
    wtrans_kernel<<<dim3(DM / 32, DM / 32), 256>>>(Wv, DM, DM, wvh, wvl);
    wtrans_kernel<<<dim3(DM / 32, DM / 32), 256>>>(Wo, DM, DM, woh, wol);
    wtrans_kernel<<<dim3(DFF / 32, DM / 32), 256>>>(W1, DM, DFF, w1h, w1l);
    wtrans_kernel<<<dim3(DM / 32, DFF / 32), 256>>>(W2, DFF, DM, w2h, w2l);

    // 2. QKV projections
    mma_gemm_kernel<1, true><<<dim3(DM / 64, NT / 128), 256>>>(
        xh, xl, DM, wqh, wql, DM, bq, nullptr, qh, ql, DM, DM);
    mma_gemm_kernel<1, true><<<dim3(DM / 64, NT / 128), 256>>>(
        xh, xl, DM, wkh, wkl, DM, bk, nullptr, kh, kl, DM, DM);
    mma_gemm_kernel<1, true><<<dim3(DM / 64, NT / 128), 256>>>(
        xh, xl, DM, wvh, wvl, DM, bv, nullptr, vh, vl, DM, DM);

    // 3. transpose V per head
    vtrans_kernel<<<dim3(SS / 64, BH), 256>>>(vh, vl, vth, vtl);

    // 4. fused flash attention -> ctx planes
    flash_attn_kernel<<<dim3(SS / 128, BH), 256, 65536>>>(
        qh, ql, kh, kl, vth, vtl, ch, cl);

    // 5. attn_out = ctx @ Wo + bo (fp32)
    mma_gemm_kernel<1, false><<<dim3(DM / 64, NT / 128), 256>>>(
        ch, cl, DM, woh, wol, DM, bo, ao, nullptr, nullptr, DM, DM);

    // 6. h = LN(x + ao)
    add_ln_kernel<true><<<NT, 256>>>(x, ao, g1, be1, hbuf, hh, hl);

    // 7. ff1 = relu(h @ W1 + b1)
    mma_gemm_kernel<2, true><<<dim3(DFF / 64, NT / 128), 256>>>(
        hh, hl, DM, w1h, w1l, DM, b1, nullptr, f1h, f1l, DFF, DM);

    // 8. ff2 = ff1 @ W2 + b2 (fp32)
    mma_gemm_kernel<1, false><<<dim3(DM / 64, NT / 128), 256>>>(
        f1h, f1l, DFF, w2h, w2l, DFF, b2, ff2, nullptr, nullptr, DM, DFF);

    // 9. out = LN(h + ff2)
    add_ln_kernel<false><<<NT, 256>>>(hbuf, ff2, g2, be2, (float*)d_out, nullptr, nullptr);
}